// round 13
// baseline (speedup 1.0000x reference)
#include <cuda_runtime.h>
#include <cstdint>

// ---------------------------------------------------------------------------
// R12: two-kernel split.
//  Kernel A (qkv_attn): one CTA per batch element, 2 CTAs/SM.
//    x A-fragments held in REGISTERS (64/thread, loaded once from global);
//    no x smem at all. Per head: one packed Wq|Wk|Wv stage (128x104),
//    QK-GEMM pass + V-GEMM pass, 3 syncthreads/head, streaming causal
//    attention; O written as tf32 A-frags to scratch (STG.128).
//  Kernel B (proj): A-frags via 16x LDG.128 from scratch; Wp staged
//    pair-interleaved so every B-frag is one conflict-free LDS.64.
// ---------------------------------------------------------------------------

namespace {

// kernel A smem (words)
constexpr int W3T = 104;                    // packed W stage stride
constexpr int KST = 36;                     // K buffer stride
constexpr int VST = 40;                     // V buffer stride
constexpr int W3_OFF = 0;
constexpr int KS_OFF = W3_OFF + 128 * W3T;  // 13312
constexpr int VS_OFF = KS_OFF + 128 * KST;  // 17920
constexpr int SMEMA_WORDS = VS_OFF + 128 * VST;  // 23040 words = 92160 B
constexpr unsigned SMEMA_BYTES = SMEMA_WORDS * 4;

// kernel B smem: Wp pair-interleaved, 64 row-pair slots x 264 words
constexpr int PST = 264;
constexpr int SMEMB_WORDS = 64 * PST;       // 16896 words = 67584 B
constexpr unsigned SMEMB_BYTES = SMEMB_WORDS * 4;

// O scratch in tf32 A-fragment order: [(b*8+w)*16 + kt][lane*4 + j]
__device__ uint32_t g_scratch[4096ull * 16 * 8 * 128];

__device__ __forceinline__ uint32_t f2tf32(float f) {
  uint32_t r;
  asm("cvt.rna.tf32.f32 %0, %1;" : "=r"(r) : "f"(f));
  return r;
}

__device__ __forceinline__ void mma8(float& d0, float& d1, float& d2, float& d3,
                                     uint32_t a0, uint32_t a1, uint32_t a2, uint32_t a3,
                                     uint32_t b0, uint32_t b1) {
  asm volatile(
      "mma.sync.aligned.m16n8k8.row.col.f32.tf32.tf32.f32 "
      "{%0,%1,%2,%3},{%4,%5,%6,%7},{%8,%9},{%0,%1,%2,%3};"
      : "+f"(d0), "+f"(d1), "+f"(d2), "+f"(d3)
      : "r"(a0), "r"(a1), "r"(a2), "r"(a3), "r"(b0), "r"(b1));
}

// m16n8 C-layout tile -> m16k8 A-layout tile (tf32). 8 shuffles, warp-uniform.
__device__ __forceinline__ void c2a(float c0, float c1, float c2, float c3,
                                    uint32_t a[4]) {
  int lane = threadIdx.x & 31;
  int qi = lane & 3;
  int s1 = (lane & ~3) | (qi >> 1);
  int s2 = s1 + 2;
  float t0 = __shfl_sync(0xffffffffu, c0, s1);
  float t1 = __shfl_sync(0xffffffffu, c1, s1);
  float t2 = __shfl_sync(0xffffffffu, c2, s1);
  float t3 = __shfl_sync(0xffffffffu, c3, s1);
  float u0 = __shfl_sync(0xffffffffu, c0, s2);
  float u1 = __shfl_sync(0xffffffffu, c1, s2);
  float u2 = __shfl_sync(0xffffffffu, c2, s2);
  float u3 = __shfl_sync(0xffffffffu, c3, s2);
  bool odd = (qi & 1);
  a[0] = f2tf32(odd ? t1 : t0);
  a[1] = f2tf32(odd ? t3 : t2);
  a[2] = f2tf32(odd ? u1 : u0);
  a[3] = f2tf32(odd ? u3 : u2);
}

// ============================ Kernel A ====================================
__global__ __launch_bounds__(256, 2)
void qkv_attn_kernel(const float* __restrict__ x,
                     const float* __restrict__ Wq, const float* __restrict__ bq,
                     const float* __restrict__ Wk, const float* __restrict__ bk,
                     const float* __restrict__ Wv, const float* __restrict__ bv) {
  extern __shared__ uint32_t sm[];
  uint32_t* W3 = sm + W3_OFF;
  uint32_t* KS = sm + KS_OFF;
  uint32_t* VS = sm + VS_OFF;

  const int tid = threadIdx.x;
  const int lane = tid & 31;
  const int w = tid >> 5;
  const int g = lane >> 2;
  const int qi = lane & 3;
  const int b = blockIdx.x;
  const int row0 = w * 16 + g;
  const int row1 = row0 + 8;

  // ---- x A-fragments -> registers (loaded once, reused for all 12 GEMMs) ----
  uint32_t A[16][4];
  {
    const float* xb = x + (size_t)b * 16384;
    #pragma unroll
    for (int kt = 0; kt < 16; kt++) {
      int c = kt * 8 + qi;
      A[kt][0] = f2tf32(__ldg(xb + row0 * 128 + c));
      A[kt][1] = f2tf32(__ldg(xb + row1 * 128 + c));
      A[kt][2] = f2tf32(__ldg(xb + row0 * 128 + c + 4));
      A[kt][3] = f2tf32(__ldg(xb + row1 * 128 + c + 4));
    }
  }

  const int nt_lim = 2 * w + 1;
  const float scale = 0.088388347648318447f;  // 128^-0.5 (CONTEXT_SIZE scaling)
  uint32_t* og = g_scratch + ((size_t)b * 8 + w) * 2048 + lane * 4;

  for (int h = 0; h < 4; h++) {
    __syncthreads();   // sync1: all prior-head attention reads (KS/VS) done

    // ---- stage Wq_h|Wk_h|Wv_h packed -> W3[128][104] ----
    {
      const float* Wsrc[3] = {Wq + h * 4096, Wk + h * 4096, Wv + h * 4096};
      #pragma unroll
      for (int m = 0; m < 3; m++) {
        const float4* wg = reinterpret_cast<const float4*>(Wsrc[m]);
        #pragma unroll
        for (int i = 0; i < 4; i++) {
          int v = tid + i * 256;
          float4 f = wg[v];
          uint32_t* p = W3 + (v >> 3) * W3T + m * 32 + ((v & 7) << 2);
          p[0] = f2tf32(f.x); p[1] = f2tf32(f.y); p[2] = f2tf32(f.z); p[3] = f2tf32(f.w);
        }
      }
    }
    __syncthreads();   // sync2: W3 visible

    // ---- QK pass: Q,K = x @ {Wq,Wk} (A from registers) ----
    float qacc[4][4], kacc[4][4];
    #pragma unroll
    for (int nt = 0; nt < 4; nt++) {
      #pragma unroll
      for (int j = 0; j < 4; j++) { qacc[nt][j] = 0.f; kacc[nt][j] = 0.f; }
    }
    #pragma unroll
    for (int kt = 0; kt < 16; kt++) {
      int brow = (kt * 8 + qi) * W3T;
      #pragma unroll
      for (int nt = 0; nt < 4; nt++) {
        int bo = brow + nt * 8 + g;
        mma8(qacc[nt][0], qacc[nt][1], qacc[nt][2], qacc[nt][3],
             A[kt][0], A[kt][1], A[kt][2], A[kt][3],
             W3[bo], W3[bo + 4 * W3T]);
        mma8(kacc[nt][0], kacc[nt][1], kacc[nt][2], kacc[nt][3],
             A[kt][0], A[kt][1], A[kt][2], A[kt][3],
             W3[bo + 32], W3[bo + 32 + 4 * W3T]);
      }
    }
    // K + bias -> KS; Q + bias -> qa (scale folded)
    uint32_t qa[4][4];
    #pragma unroll
    for (int nt = 0; nt < 4; nt++) {
      int c = nt * 8 + 2 * qi;
      float2 bk2 = *reinterpret_cast<const float2*>(bk + h * 32 + c);
      float2 bq2 = *reinterpret_cast<const float2*>(bq + h * 32 + c);
      KS[row0 * KST + c]     = f2tf32(kacc[nt][0] + bk2.x);
      KS[row0 * KST + c + 1] = f2tf32(kacc[nt][1] + bk2.y);
      KS[row1 * KST + c]     = f2tf32(kacc[nt][2] + bk2.x);
      KS[row1 * KST + c + 1] = f2tf32(kacc[nt][3] + bk2.y);
      c2a((qacc[nt][0] + bq2.x) * scale, (qacc[nt][1] + bq2.y) * scale,
          (qacc[nt][2] + bq2.x) * scale, (qacc[nt][3] + bq2.y) * scale, qa[nt]);
    }

    // ---- V pass: V = x @ Wv ----
    float vacc[4][4];
    #pragma unroll
    for (int nt = 0; nt < 4; nt++)
      { vacc[nt][0] = 0.f; vacc[nt][1] = 0.f; vacc[nt][2] = 0.f; vacc[nt][3] = 0.f; }
    #pragma unroll
    for (int kt = 0; kt < 16; kt++) {
      int brow = (kt * 8 + qi) * W3T + 64;
      #pragma unroll
      for (int nt = 0; nt < 4; nt++) {
        int bo = brow + nt * 8 + g;
        mma8(vacc[nt][0], vacc[nt][1], vacc[nt][2], vacc[nt][3],
             A[kt][0], A[kt][1], A[kt][2], A[kt][3],
             W3[bo], W3[bo + 4 * W3T]);
      }
    }
    #pragma unroll
    for (int nt = 0; nt < 4; nt++) {
      int c = nt * 8 + 2 * qi;
      float2 bv2 = *reinterpret_cast<const float2*>(bv + h * 32 + c);
      VS[row0 * VST + c]     = f2tf32(vacc[nt][0] + bv2.x);
      VS[row0 * VST + c + 1] = f2tf32(vacc[nt][1] + bv2.y);
      VS[row1 * VST + c]     = f2tf32(vacc[nt][2] + bv2.x);
      VS[row1 * VST + c + 1] = f2tf32(vacc[nt][3] + bv2.y);
    }
    __syncthreads();   // sync3: K (KS) and V (VS) visible to all warps

    // ---- streaming causal attention ----
    float oacc[4][4];
    #pragma unroll
    for (int nt = 0; nt < 4; nt++)
      { oacc[nt][0] = 0.f; oacc[nt][1] = 0.f; oacc[nt][2] = 0.f; oacc[nt][3] = 0.f; }
    float sum0 = 0.f, sum1 = 0.f;

    #pragma unroll
    for (int nt = 0; nt < 16; nt++) {
      if (nt <= nt_lim) {
        float s0 = 0.f, s1 = 0.f, s2 = 0.f, s3 = 0.f;
        int krow = (nt * 8 + g) * KST;
        #pragma unroll
        for (int kt = 0; kt < 4; kt++) {
          int bo = krow + kt * 8 + qi;
          mma8(s0, s1, s2, s3,
               qa[kt][0], qa[kt][1], qa[kt][2], qa[kt][3],
               KS[bo], KS[bo + 4]);
        }
        int c = nt * 8 + 2 * qi;
        float p0 = (c     > row0) ? 0.f : __expf(s0);
        float p1 = (c + 1 > row0) ? 0.f : __expf(s1);
        float p2 = (c     > row1) ? 0.f : __expf(s2);
        float p3 = (c + 1 > row1) ? 0.f : __expf(s3);
        sum0 += p0 + p1;
        sum1 += p2 + p3;

        uint32_t pa[4];
        c2a(p0, p1, p2, p3, pa);
        int brow = (nt * 8 + qi) * VST;
        #pragma unroll
        for (int ntv = 0; ntv < 4; ntv++) {
          int bo = brow + ntv * 8 + g;
          mma8(oacc[ntv][0], oacc[ntv][1], oacc[ntv][2], oacc[ntv][3],
               pa[0], pa[1], pa[2], pa[3], VS[bo], VS[bo + 4 * VST]);
        }
      }
    }

    sum0 += __shfl_xor_sync(0xffffffffu, sum0, 1);
    sum0 += __shfl_xor_sync(0xffffffffu, sum0, 2);
    sum1 += __shfl_xor_sync(0xffffffffu, sum1, 1);
    sum1 += __shfl_xor_sync(0xffffffffu, sum1, 2);
    float inv0 = __fdividef(1.0f, sum0);
    float inv1 = __fdividef(1.0f, sum1);

    #pragma unroll
    for (int nt = 0; nt < 4; nt++) {
      uint32_t oa[4];
      c2a(oacc[nt][0] * inv0, oacc[nt][1] * inv0,
          oacc[nt][2] * inv1, oacc[nt][3] * inv1, oa);
      *reinterpret_cast<uint4*>(og + (h * 4 + nt) * 128) =
          make_uint4(oa[0], oa[1], oa[2], oa[3]);
    }
  }
}

// ============================ Kernel B ====================================
// out = O @ Wp + bp.  A-frags from scratch (LDG.128); Wp pair-interleaved
// so each B-frag is one conflict-free LDS.64.
__global__ __launch_bounds__(256, 2)
void proj_kernel(const float* __restrict__ Wp, const float* __restrict__ bp,
                 float* __restrict__ out) {
  extern __shared__ uint32_t sm[];

  const int tid = threadIdx.x;
  const int lane = tid & 31;
  const int w = tid >> 5;
  const int g = lane >> 2;
  const int qi = lane & 3;
  const int b = blockIdx.x;
  const int row0 = w * 16 + g;
  const int row1 = row0 + 8;

  // stage Wp pair-interleaved: row d -> slot (d>>3)*4+(d&3), half (d>>2)&1
  {
    const float4* wg = reinterpret_cast<const float4*>(Wp);
    #pragma unroll
    for (int i = 0; i < 16; i++) {
      int v = tid + i * 256;
      float4 f = wg[v];
      int d = v >> 5;
      int n0 = (v & 31) << 2;
      int pr = ((d >> 3) << 2) + (d & 3);
      int hf = (d >> 2) & 1;
      uint32_t* p = sm + pr * PST + (n0 << 1) + hf;
      p[0] = f2tf32(f.x); p[2] = f2tf32(f.y); p[4] = f2tf32(f.z); p[6] = f2tf32(f.w);
    }
  }

  // A-frags: 16 coalesced LDG.128 from scratch
  uint32_t A[16][4];
  const uint32_t* ab = g_scratch + ((size_t)b * 8 + w) * 2048 + lane * 4;
  #pragma unroll
  for (int kt = 0; kt < 16; kt++) {
    uint4 v = *reinterpret_cast<const uint4*>(ab + kt * 128);
    A[kt][0] = v.x; A[kt][1] = v.y; A[kt][2] = v.z; A[kt][3] = v.w;
  }
  __syncthreads();

  float* og = out + (size_t)b * 16384;
  #pragma unroll
  for (int half = 0; half < 2; half++) {
    float acc[8][4];
    #pragma unroll
    for (int nt8 = 0; nt8 < 8; nt8++) {
      int c = (half * 8 + nt8) * 8 + 2 * qi;
      float2 bp2 = *reinterpret_cast<const float2*>(bp + c);
      acc[nt8][0] = bp2.x; acc[nt8][1] = bp2.y; acc[nt8][2] = bp2.x; acc[nt8][3] = bp2.y;
    }
    #pragma unroll
    for (int kt = 0; kt < 16; kt++) {
      int brow = (kt * 4 + qi) * PST;       // rows (8kt+qi, 8kt+qi+4) adjacent
      #pragma unroll
      for (int nt8 = 0; nt8 < 8; nt8++) {
        uint2 B = *reinterpret_cast<const uint2*>(
            sm + brow + (((half * 8 + nt8) * 8 + g) << 1));
        mma8(acc[nt8][0], acc[nt8][1], acc[nt8][2], acc[nt8][3],
             A[kt][0], A[kt][1], A[kt][2], A[kt][3], B.x, B.y);
      }
    }
    #pragma unroll
    for (int nt8 = 0; nt8 < 8; nt8++) {
      int c = (half * 8 + nt8) * 8 + 2 * qi;
      *reinterpret_cast<float2*>(og + row0 * 128 + c) = make_float2(acc[nt8][0], acc[nt8][1]);
      *reinterpret_cast<float2*>(og + row1 * 128 + c) = make_float2(acc[nt8][2], acc[nt8][3]);
    }
  }
}

}  // namespace

extern "C" void kernel_launch(void* const* d_in, const int* in_sizes, int n_in,
                              void* d_out, int out_size) {
  const float* x  = (const float*)d_in[0];
  const float* Wq = (const float*)d_in[1];
  const float* bq = (const float*)d_in[2];
  const float* Wk = (const float*)d_in[3];
  const float* bk = (const float*)d_in[4];
  const float* Wv = (const float*)d_in[5];
  const float* bv = (const float*)d_in[6];
  const float* Wp = (const float*)d_in[7];
  const float* bp = (const float*)d_in[8];
  float* out = (float*)d_out;

  int batches = in_sizes[0] / (128 * 128);  // 4096

  cudaFuncSetAttribute(qkv_attn_kernel,
                       cudaFuncAttributeMaxDynamicSharedMemorySize, SMEMA_BYTES);
  cudaFuncSetAttribute(proj_kernel,
                       cudaFuncAttributeMaxDynamicSharedMemorySize, SMEMB_BYTES);

  qkv_attn_kernel<<<batches, 256, SMEMA_BYTES>>>(x, Wq, bq, Wk, bk, Wv, bv);
  proj_kernel<<<batches, 256, SMEMB_BYTES>>>(Wp, bp, out);
}